// round 6
// baseline (speedup 1.0000x reference)
#include <cuda_runtime.h>
#include <cuda_fp16.h>
#include <math.h>
#include <stdint.h>

#define NB 8
#define LQ 1024
#define HH 16
#define DD 64
#define EE 1024
#define ROWS (NB*HH*LQ)   // 131072 head-rows

// Scratch (static device globals — no allocation)
__device__ __half g_q[ROWS*DD];
__device__ __half g_k[ROWS*DD];
__device__ __half g_v[ROWS*DD];   // v' = x @ (Wv@Wfc), stored TRANSPOSED: [n,h,d,l]
__device__ float  g_Wvf[DD*DD];

__device__ __forceinline__ void mma_f16(float d[4],
        uint32_t a0, uint32_t a1, uint32_t a2, uint32_t a3,
        uint32_t b0, uint32_t b1) {
    asm volatile(
        "mma.sync.aligned.m16n8k16.row.col.f32.f16.f16.f32 "
        "{%0,%1,%2,%3},{%4,%5,%6,%7},{%8,%9},{%0,%1,%2,%3};"
        : "+f"(d[0]), "+f"(d[1]), "+f"(d[2]), "+f"(d[3])
        : "r"(a0), "r"(a1), "r"(a2), "r"(a3), "r"(b0), "r"(b1));
}

#define CP_ASYNC16(dst_u32, src_ptr) \
    asm volatile("cp.async.cg.shared.global [%0], [%1], 16;" :: "r"(dst_u32), "l"(src_ptr))
#define CP_COMMIT() asm volatile("cp.async.commit_group;" ::: "memory")
#define CP_WAIT(N)  asm volatile("cp.async.wait_group %0;" :: "n"(N) : "memory")

// ---------------------------------------------------------------------------
// prep: Wvf = Wv @ Wfc  (64x64 @ 64x64)
// ---------------------------------------------------------------------------
__global__ __launch_bounds__(1024) void prep_kernel(const float* __restrict__ Wv,
                                                    const float* __restrict__ Wfc) {
    __shared__ float wv[64*64];
    __shared__ float wf[64*64];
    int tid = threadIdx.x;
    for (int i = tid; i < 4096; i += 1024) { wv[i] = Wv[i]; wf[i] = Wfc[i]; }
    __syncthreads();
    int r = tid >> 4, c4 = (tid & 15) << 2;
    float4 acc = {0.f, 0.f, 0.f, 0.f};
    #pragma unroll 8
    for (int u = 0; u < 64; u++) {
        float a = wv[r*64 + u];
        float4 b = *(const float4*)&wf[u*64 + c4];
        acc.x += a*b.x; acc.y += a*b.y; acc.z += a*b.z; acc.w += a*b.w;
    }
    *(float4*)&g_Wvf[r*64 + c4] = acc;
}

// ---------------------------------------------------------------------------
// projection: per (n, h, 64-row l-tile): q = x@(Wq*0.06/32), k = x@Wk, v' = x@Wvf
// outputs fp16; g_v written transposed ([d][l])
// ---------------------------------------------------------------------------
__global__ __launch_bounds__(256) void proj_kernel(const float* __restrict__ x,
                                                   const float* __restrict__ Wq,
                                                   const float* __restrict__ Wk) {
    extern __shared__ float sm[];
    float* xs = sm;               // 64*65
    float* ws = xs + 64*65;       // 3 * 64*65
    float* os = ws + 3*64*65;     // 64*64
    const int tid = threadIdx.x;
    const int bid = blockIdx.x;
    const int n = bid >> 8, h = (bid >> 4) & 15, lt = bid & 15;
    const int l0 = lt << 6;
    const float qs = 0.06f / 32.0f;

    for (int idx = tid; idx < 1024; idx += 256) {
        int l = idx >> 4, t4 = (idx & 15) << 2;
        float4 v = *(const float4*)&x[(n*LQ + l0 + l)*EE + (h << 6) + t4];
        float* p = &xs[l*65 + t4];
        p[0] = v.x; p[1] = v.y; p[2] = v.z; p[3] = v.w;
    }
    for (int idx = tid; idx < 4096; idx += 256) {
        int t = idx >> 6, d = idx & 63;
        ws[t*65 + d]            = Wq[idx] * qs;
        ws[64*65 + t*65 + d]    = Wk[idx];
        ws[2*64*65 + t*65 + d]  = g_Wvf[idx];
    }
    __syncthreads();

    const int tl = tid & 15, td = tid >> 4;
    for (int w = 0; w < 3; w++) {
        const float* W = ws + w*64*65;
        float acc[4][4] = {};
        for (int t = 0; t < 64; t++) {
            float xv[4], wv[4];
            #pragma unroll
            for (int a = 0; a < 4; a++) xv[a] = xs[(tl*4 + a)*65 + t];
            #pragma unroll
            for (int b = 0; b < 4; b++) wv[b] = W[t*65 + td*4 + b];
            #pragma unroll
            for (int a = 0; a < 4; a++)
                #pragma unroll
                for (int b = 0; b < 4; b++) acc[a][b] += xv[a] * wv[b];
        }
        if (w < 2) {
            #pragma unroll
            for (int a = 0; a < 4; a++)
                #pragma unroll
                for (int b = 0; b < 4; b++)
                    os[(tl*4 + a)*64 + td*4 + b] = acc[a][b];
        } else {
            #pragma unroll
            for (int a = 0; a < 4; a++)
                #pragma unroll
                for (int b = 0; b < 4; b++)
                    os[(td*4 + b)*64 + tl*4 + a] = acc[a][b];
        }
        __syncthreads();
        if (w < 2) {
            __half* gp = (w == 0 ? g_q : g_k) + ((n*HH + h)*LQ + l0)*DD;
            for (int idx = tid; idx < 2048; idx += 256) {
                int row = idx >> 5, d2 = (idx & 31) << 1;
                __half2 hv = __floats2half2_rn(os[row*64 + d2], os[row*64 + d2 + 1]);
                *(__half2*)(gp + row*64 + d2) = hv;
            }
        } else {
            __half* gp = g_v + ((n*HH + h)*DD)*LQ + l0;
            for (int idx = tid; idx < 2048; idx += 256) {
                int d = idx >> 5, l2 = (idx & 31) << 1;
                __half2 hv = __floats2half2_rn(os[d*64 + l2], os[d*64 + l2 + 1]);
                *(__half2*)(gp + d*LQ + l2) = hv;
            }
        }
        __syncthreads();
    }
}

// ---------------------------------------------------------------------------
// attention v4: 32-query block, 512 threads, 16 warps.
//  phase1: warp = pure n-split (8 key-cols/chunk, all 32 rows). No B dup.
//          qf[2][4][4] (32 regs), acc[8][2][4] (64 regs).
//  softmax: per-thread rows {g,g+8,g+16,g+24}; quad shfl + 32x16 smem reduce.
//          attn written DIRECTLY from registers (float2, 32B sectors).
//          P also stored to swizzled fp16 Ph for phase 3.
//  phase3: warp = (kl 0..7) x (nh 0..1): keys kl*16 of each chunk, 32 dims.
//          Partials in regs across chunks; final 8-way reduce via smem
//          buffer overlaid on dead Ph/Qs (stride 68 floats).
// smem map (bytes):
//   PH 0..65536 | QS 65536..69632 | KB 69632..102400 | VB 102400..135168
//   REDM 135168..137216 | REDS 137216..139264   TOT=139264
//   reduce overlay: [0, 69632) = 8 * 32 * 68 * 4
// ---------------------------------------------------------------------------
#define SMEM_PH   0
#define SMEM_QS   65536
#define SMEM_KB   69632
#define SMEM_VB   102400
#define SMEM_REDM 135168
#define SMEM_REDS 137216
#define SMEM_TOT  139264

__global__ __launch_bounds__(512, 1) void attn_kernel(float* __restrict__ attn,
                                                      float* __restrict__ out) {
    extern __shared__ char smraw[];
    __half* Ph   = (__half*)(smraw + SMEM_PH);
    __half* Qs   = (__half*)(smraw + SMEM_QS);
    float*  redM = (float*)(smraw + SMEM_REDM);
    float*  redS = (float*)(smraw + SMEM_REDS);
    float*  red  = (float*)(smraw);               // overlay, used after Ph dead
    const uint32_t sbase = (uint32_t)__cvta_generic_to_shared(smraw);

    const int tid = threadIdx.x, w = tid >> 5, lane = tid & 31;
    const int bid = blockIdx.x;
    const int n = bid >> 9, h = (bid >> 5) & 15, qb = bid & 31;
    const int q0 = qb << 5;
    const int base = (n*HH + h)*LQ;
    const int g = lane >> 2, tg = lane & 3;

    const __half* kg0 = g_k + (size_t)base * DD;
    const __half* vg0 = g_v + (size_t)(n*HH + h) * DD * LQ;

    // issue K chunk 0
    #pragma unroll
    for (int t = tid; t < 1024; t += 512) {
        int r = t >> 3, c8 = t & 7;
        CP_ASYNC16(sbase + SMEM_KB + (r*64 + ((c8 ^ (r & 7)) << 3))*2,
                   kg0 + r*64 + c8*8);
    }
    CP_COMMIT();

    // load Q tile (32x64 half), swizzled
    if (tid < 256) {
        int r = tid >> 3, c8 = tid & 7;
        const uint4* src = (const uint4*)(g_q + (size_t)(base + q0 + r)*DD) + c8;
        *(uint4*)(Qs + r*64 + ((c8 ^ (r & 7)) << 3)) = *src;
    }
    __syncthreads();

    // Q fragments: all 32 rows (2 row-tiles) x 4 k-steps
    uint32_t qf[2][4][4];
    #pragma unroll
    for (int rt = 0; rt < 2; rt++) {
        int r0 = rt*16 + g, r1 = r0 + 8;
        #pragma unroll
        for (int kk = 0; kk < 4; kk++) {
            int c8a = 2*kk, c8b = 2*kk + 1;
            qf[rt][kk][0] = *(const uint32_t*)(Qs + r0*64 + ((c8a ^ g) << 3) + 2*tg);
            qf[rt][kk][1] = *(const uint32_t*)(Qs + r1*64 + ((c8a ^ g) << 3) + 2*tg);
            qf[rt][kk][2] = *(const uint32_t*)(Qs + r0*64 + ((c8b ^ g) << 3) + 2*tg);
            qf[rt][kk][3] = *(const uint32_t*)(Qs + r1*64 + ((c8b ^ g) << 3) + 2*tg);
        }
    }

    // ---- phase 1: scores into registers (warp owns cols w*8 of each chunk) ----
    float acc[8][2][4];
    #pragma unroll
    for (int c = 0; c < 8; c++)
        #pragma unroll
        for (int rt = 0; rt < 2; rt++)
            #pragma unroll
            for (int j = 0; j < 4; j++) acc[c][rt][j] = 0.f;

    const int krow = w*8 + g;   // B n-row for this warp (key within chunk)
    #pragma unroll
    for (int c = 0; c < 8; c++) {
        CP_WAIT(0);
        __syncthreads();
        if (c < 7) {          // prefetch next K chunk
            const __half* kc = kg0 + (size_t)(c + 1)*128*DD;
            #pragma unroll
            for (int t = tid; t < 1024; t += 512) {
                int r = t >> 3, c8 = t & 7;
                CP_ASYNC16(sbase + SMEM_KB + ((c + 1) & 1)*16384
                           + (r*64 + ((c8 ^ (r & 7)) << 3))*2,
                           kc + r*64 + c8*8);
            }
            CP_COMMIT();
        } else {              // prefetch V chunk 0
            #pragma unroll
            for (int t = tid; t < 1024; t += 512) {
                int r = t >> 4, c8 = t & 15;
                CP_ASYNC16(sbase + SMEM_VB + (r*128 + ((c8 ^ (r & 7)) << 3))*2,
                           vg0 + r*LQ + c8*8);
            }
            CP_COMMIT();
        }
        const __half* Kc = (const __half*)(smraw + SMEM_KB + (c & 1)*16384);
        #pragma unroll
        for (int kk = 0; kk < 4; kk++) {
            uint32_t b0 = *(const uint32_t*)(Kc + krow*64 + (((2*kk)   ^ g) << 3) + 2*tg);
            uint32_t b1 = *(const uint32_t*)(Kc + krow*64 + (((2*kk+1) ^ g) << 3) + 2*tg);
            #pragma unroll
            for (int rt = 0; rt < 2; rt++)
                mma_f16(acc[c][rt], qf[rt][kk][0], qf[rt][kk][1],
                        qf[rt][kk][2], qf[rt][kk][3], b0, b1);
        }
    }
    // issue V chunk 1
    #pragma unroll
    for (int t = tid; t < 1024; t += 512) {
        int r = t >> 4, c8 = t & 15;
        CP_ASYNC16(sbase + SMEM_VB + 16384 + (r*128 + ((c8 ^ (r & 7)) << 3))*2,
                   vg0 + r*LQ + 128 + c8*8);
    }
    CP_COMMIT();

    // ---- phase 2: softmax ----
    // thread rows: row(rt,z) = rt*16 + z*8 + g ; cols c*128 + w*8 + 2tg{,+1}
    float mx[2][2];
    #pragma unroll
    for (int rt = 0; rt < 2; rt++)
        #pragma unroll
        for (int z = 0; z < 2; z++) {
            float m = -1e30f;
            #pragma unroll
            for (int c = 0; c < 8; c++)
                m = fmaxf(m, fmaxf(acc[c][rt][2*z], acc[c][rt][2*z + 1]));
            m = fmaxf(m, __shfl_xor_sync(0xffffffffu, m, 1));
            m = fmaxf(m, __shfl_xor_sync(0xffffffffu, m, 2));
            mx[rt][z] = m;
        }
    if (tg == 0) {
        #pragma unroll
        for (int rt = 0; rt < 2; rt++)
            #pragma unroll
            for (int z = 0; z < 2; z++)
                redM[(rt*16 + z*8 + g)*16 + w] = mx[rt][z];
    }
    __syncthreads();
    float sum[2][2];
    #pragma unroll
    for (int rt = 0; rt < 2; rt++)
        #pragma unroll
        for (int z = 0; z < 2; z++) {
            int row = rt*16 + z*8 + g;
            float m = -1e30f;
            #pragma unroll
            for (int k = 0; k < 16; k++) m = fmaxf(m, redM[row*16 + k]);
            mx[rt][z] = m;
            float s = 0.f;
            #pragma unroll
            for (int c = 0; c < 8; c++) {
                float e0 = __expf(acc[c][rt][2*z]     - m);
                float e1 = __expf(acc[c][rt][2*z + 1] - m);
                acc[c][rt][2*z]     = e0;
                acc[c][rt][2*z + 1] = e1;
                s += e0 + e1;
            }
            s += __shfl_xor_sync(0xffffffffu, s, 1);
            s += __shfl_xor_sync(0xffffffffu, s, 2);
            sum[rt][z] = s;
        }
    if (tg == 0) {
        #pragma unroll
        for (int rt = 0; rt < 2; rt++)
            #pragma unroll
            for (int z = 0; z < 2; z++)
                redS[(rt*16 + z*8 + g)*16 + w] = sum[rt][z];
    }
    __syncthreads();
    float inv[2][2];
    #pragma unroll
    for (int rt = 0; rt < 2; rt++)
        #pragma unroll
        for (int z = 0; z < 2; z++) {
            int row = rt*16 + z*8 + g;
            float s = 0.f;
            #pragma unroll
            for (int k = 0; k < 16; k++) s += redS[row*16 + k];
            inv[rt][z] = 1.0f / s;
        }

    // normalize: write attn directly (fp32) + Ph (fp16, swizzled)
    #pragma unroll
    for (int rt = 0; rt < 2; rt++)
        #pragma unroll
        for (int z = 0; z < 2; z++) {
            int row = rt*16 + z*8 + g;
            float iv = inv[rt][z];
            float* arow = attn + (size_t)(base + q0 + row)*1024 + w*8 + 2*tg;
            #pragma unroll
            for (int c = 0; c < 8; c++) {
                float p0 = acc[c][rt][2*z]     * iv;
                float p1 = acc[c][rt][2*z + 1] * iv;
                *(float2*)(arow + c*128) = make_float2(p0, p1);
                __half2 hp = __floats2half2_rn(p0, p1);
                *(uint32_t*)(Ph + row*1024 + (((c*16 + w) ^ g) << 3) + 2*tg)
                    = *(uint32_t*)&hp;
            }
        }

    // ---- phase 3: out = P @ V'. warp = (kl = w&7 keys, nh = w>>3 dims) ----
    const int kl = w & 7, nh = w >> 3;
    float oacc[2][4][4];
    #pragma unroll
    for (int rt = 0; rt < 2; rt++)
        #pragma unroll
        for (int nt = 0; nt < 4; nt++)
            #pragma unroll
            for (int j = 0; j < 4; j++) oacc[rt][nt][j] = 0.f;

    #pragma unroll
    for (int c = 0; c < 8; c++) {
        CP_WAIT(1);
        if (c == 7) { CP_WAIT(0); }
        __syncthreads();
        const __half* Vc = (const __half*)(smraw + SMEM_VB + (c & 1)*16384);
        // A frags: rows 0..31, keys c*128 + kl*16 + [0,16)
        int c8a = c*16 + 2*kl, c8b = c8a + 1;
        uint32_t af[2][4];
        #pragma unroll
        for (int rt = 0; rt < 2; rt++) {
            int r0 = rt*16 + g, r1 = r0 + 8;
            af[rt][0] = *(const uint32_t*)(Ph + r0*1024 + ((c8a ^ g) << 3) + 2*tg);
            af[rt][1] = *(const uint32_t*)(Ph + r1*1024 + ((c8a ^ g) << 3) + 2*tg);
            af[rt][2] = *(const uint32_t*)(Ph + r0*1024 + ((c8b ^ g) << 3) + 2*tg);
            af[rt][3] = *(const uint32_t*)(Ph + r1*1024 + ((c8b ^ g) << 3) + 2*tg);
        }
        #pragma unroll
        for (int nt = 0; nt < 4; nt++) {
            int vrow = nh*32 + nt*8 + g;   // dim index (vrow & 7 == g)
            uint32_t b0 = *(const uint32_t*)(Vc + vrow*128 + (((2*kl)   ^ g) << 3) + 2*tg);
            uint32_t b1 = *(const uint32_t*)(Vc + vrow*128 + (((2*kl+1) ^ g) << 3) + 2*tg);
            #pragma unroll
            for (int rt = 0; rt < 2; rt++)
                mma_f16(oacc[rt][nt], af[rt][0], af[rt][1], af[rt][2], af[rt][3], b0, b1);
        }
        __syncthreads();
        if (c + 2 < 8) {   // prefetch V chunk c+2 into buffer (c&1)
            const __half* vc = vg0 + (size_t)(c + 2)*128;
            #pragma unroll
            for (int t = tid; t < 1024; t += 512) {
                int r = t >> 4, c8 = t & 15;
                CP_ASYNC16(sbase + SMEM_VB + (c & 1)*16384
                           + (r*128 + ((c8 ^ (r & 7)) << 3))*2,
                           vc + r*LQ + c8*8);
            }
            CP_COMMIT();
        }
    }

    // ---- k-split reduce: partials -> red overlay (stride 68), then sum ----
    __syncthreads();   // all Ph reads done; overlay becomes writable
    #pragma unroll
    for (int rt = 0; rt < 2; rt++)
        #pragma unroll
        for (int nt = 0; nt < 4; nt++) {
            int d0 = nh*32 + nt*8 + 2*tg;
            int r0 = rt*16 + g, r1 = r0 + 8;
            *(float2*)&red[kl*2176 + r0*68 + d0] = make_float2(oacc[rt][nt][0], oacc[rt][nt][1]);
            *(float2*)&red[kl*2176 + r1*68 + d0] = make_float2(oacc[rt][nt][2], oacc[rt][nt][3]);
        }
    __syncthreads();
    {
        int row = tid >> 4, d4 = (tid & 15) << 2;
        float4 s = make_float4(0.f, 0.f, 0.f, 0.f);
        #pragma unroll
        for (int k = 0; k < 8; k++) {
            float4 v = *(const float4*)&red[k*2176 + row*68 + d4];
            s.x += v.x; s.y += v.y; s.z += v.z; s.w += v.w;
        }
        *(float4*)&out[((size_t)(n*LQ + q0 + row)*HH + h)*DD + d4] = s;
    }
}

// ---------------------------------------------------------------------------
extern "C" void kernel_launch(void* const* d_in, const int* in_sizes, int n_in,
                              void* d_out, int out_size) {
    const float* x   = (const float*)d_in[0];
    const float* Wq  = (const float*)d_in[1];
    const float* Wk  = (const float*)d_in[2];
    const float* Wv  = (const float*)d_in[3];
    const float* Wfc = (const float*)d_in[4];

    float* out  = (float*)d_out;
    float* attn = out + (size_t)NB * LQ * EE;   // out first, then attn

    prep_kernel<<<1, 1024>>>(Wv, Wfc);

    size_t proj_smem = (size_t)(4*64*65 + 64*64) * sizeof(float);   // 82944
    cudaFuncSetAttribute(proj_kernel,
                         cudaFuncAttributeMaxDynamicSharedMemorySize,
                         (int)proj_smem);
    proj_kernel<<<NB*HH*16, 256, proj_smem>>>(x, Wq, Wk);

    cudaFuncSetAttribute(attn_kernel,
                         cudaFuncAttributeMaxDynamicSharedMemorySize,
                         SMEM_TOT);
    attn_kernel<<<NB*HH*32, 512, SMEM_TOT>>>(attn, out);
}